// round 12
// baseline (speedup 1.0000x reference)
#include <cuda_runtime.h>
#include <cuda_fp16.h>
#include <math.h>
#include <stdint.h>

// Problem constants
#define N_TOK 16384
#define DIM   768
#define NEXP  8
#define HID   2048
#define CAP   5120
#define NK    (N_TOK*2)
#define NSLOT (NEXP*CAP)
#define NSEG  64
#define SEGSZ (NK/NSEG)

#define W13N (NEXP*2*HID*DIM)
#define W2N  (NEXP*DIM*HID)

// ---------------- device scratch ----------------
__device__ int    g_topk_e[NK];
__device__ float  g_topk_w[NK];
__device__ int    g_count[NEXP];
__device__ int    g_slot_token[NSLOT];
__device__ float  g_slot_w[NSLOT];
__device__ int    g_seg_hist[NSEG][NEXP];
__device__ int    g_seg_base[NSEG][NEXP];
__device__ __half g_zb[(size_t)N_TOK*DIM];
__device__ __half g_h[(size_t)NSLOT*HID];
__device__ __half g_w13h[W13N];
__device__ __half g_w2h[W2N];

// ---------------- helpers ----------------
__device__ __forceinline__ uint32_t smem_u32(const void* p) {
    uint32_t a;
    asm("{ .reg .u64 t; cvta.to.shared.u64 t, %1; cvt.u32.u64 %0, t; }" : "=r"(a) : "l"(p));
    return a;
}
#define CP_ASYNC16(s, g) \
    asm volatile("cp.async.cg.shared.global [%0], [%1], 16;" :: "r"(s), "l"(g))
#define CP_COMMIT() asm volatile("cp.async.commit_group;")
#define CP_WAIT1()  asm volatile("cp.async.wait_group 1;")

#define LDSM4(r0, r1, r2, r3, addr) \
    asm volatile("ldmatrix.sync.aligned.m8n8.x4.shared.b16 {%0,%1,%2,%3}, [%4];" \
        : "=r"(r0), "=r"(r1), "=r"(r2), "=r"(r3) : "r"(addr))

__device__ __forceinline__ void mma16(float* c, const uint32_t* a, const uint32_t* b) {
    asm("mma.sync.aligned.m16n8k16.row.col.f32.f16.f16.f32 "
        "{%0,%1,%2,%3}, {%4,%5,%6,%7}, {%8,%9}, {%0,%1,%2,%3};"
        : "+f"(c[0]), "+f"(c[1]), "+f"(c[2]), "+f"(c[3])
        : "r"(a[0]), "r"(a[1]), "r"(a[2]), "r"(a[3]), "r"(b[0]), "r"(b[1]));
}

// ---------------- w13 * norm_w -> half ----------------
__global__ __launch_bounds__(256) void cvt_w13_kernel(const float* __restrict__ src,
                                                      const float* __restrict__ norm_w,
                                                      __half* __restrict__ dst) {
    int i = blockIdx.x * 256 + threadIdx.x;
    int stride = gridDim.x * 256;
    const int ROW4 = DIM / 4;
    for (; i < W13N/4; i += stride) {
        int col4 = i % ROW4;
        int e = i / (2 * HID * ROW4);
        float4 v = ((const float4*)src)[i];
        float4 nw = ((const float4*)(norm_w + e * DIM))[col4];
        __half2 h0 = __floats2half2_rn(v.x * nw.x, v.y * nw.y);
        __half2 h1 = __floats2half2_rn(v.z * nw.z, v.w * nw.w);
        uint2 pk;
        pk.x = *(uint32_t*)&h0;  pk.y = *(uint32_t*)&h1;
        ((uint2*)dst)[i] = pk;
    }
}

// ---------------- w2 -> half ----------------
__global__ __launch_bounds__(256) void cvt_half_kernel(const float* __restrict__ src,
                                                       __half* __restrict__ dst, int n4) {
    int i = blockIdx.x * 256 + threadIdx.x;
    int stride = gridDim.x * 256;
    for (; i < n4; i += stride) {
        float4 v = ((const float4*)src)[i];
        __half2 h0 = __floats2half2_rn(v.x, v.y);
        __half2 h1 = __floats2half2_rn(v.z, v.w);
        uint2 pk;
        pk.x = *(uint32_t*)&h0;  pk.y = *(uint32_t*)&h1;
        ((uint2*)dst)[i] = pk;
    }
}

// ---------------- fused router + prep ----------------
__global__ __launch_bounds__(256) void router_prep_kernel(const float* __restrict__ x,
                                                          const float* __restrict__ gate_w) {
    __shared__ float gw[NEXP*DIM];
    int t = threadIdx.x;
    for (int i = t; i < NEXP*DIM; i += 256) gw[i] = gate_w[i];
    __syncthreads();
    int warp = t >> 5, lane = t & 31;
    int token = blockIdx.x * 8 + warp;
    const float* xr = x + (size_t)token * DIM;

    float xv[DIM/32];
    float acc[NEXP];
    float ss = 0.f;
    #pragma unroll
    for (int e = 0; e < NEXP; e++) acc[e] = 0.f;
    #pragma unroll
    for (int i = 0; i < DIM/32; i++) {
        float v = xr[lane + 32*i];
        xv[i] = v;
        ss += v * v;
        #pragma unroll
        for (int e = 0; e < NEXP; e++) acc[e] += v * gw[e*DIM + lane + 32*i];
    }
    #pragma unroll
    for (int off = 16; off; off >>= 1) ss += __shfl_xor_sync(0xffffffffu, ss, off);
    float scale = 2.f * rsqrtf(4.f * ss / (float)DIM + 1e-6f);
    __half* zr = g_zb + (size_t)token * DIM;
    #pragma unroll
    for (int i = 0; i < DIM/32; i++)
        zr[lane + 32*i] = __float2half_rn(xv[i] * scale);

    #pragma unroll
    for (int e = 0; e < NEXP; e++) {
        #pragma unroll
        for (int off = 16; off; off >>= 1)
            acc[e] += __shfl_xor_sync(0xffffffffu, acc[e], off);
    }
    if (lane == 0) {
        int i0 = 0;
        #pragma unroll
        for (int e = 1; e < NEXP; e++) if (acc[e] > acc[i0]) i0 = e;
        int i1 = -1;
        #pragma unroll
        for (int e = 0; e < NEXP; e++) {
            if (e == i0) continue;
            if (i1 < 0 || acc[e] > acc[i1]) i1 = e;
        }
        float l0 = acc[i0], l1 = acc[i1];
        g_topk_e[2*token]   = i0;  g_topk_e[2*token+1] = i1;
        g_topk_w[2*token]   = 1.f / (1.f + expf(l1 - l0));
        g_topk_w[2*token+1] = 1.f / (1.f + expf(l0 - l1));
    }
}

// ---------------- dispatch ----------------
__global__ __launch_bounds__(256) void disp_count_kernel() {
    __shared__ int h[NEXP];
    int t = threadIdx.x, b = blockIdx.x;
    if (t < NEXP) h[t] = 0;
    __syncthreads();
    int2 ev = *(const int2*)(g_topk_e + b * SEGSZ + 2 * t);
    atomicAdd(&h[ev.x], 1);
    atomicAdd(&h[ev.y], 1);
    __syncthreads();
    if (t < NEXP) g_seg_hist[b][t] = h[t];
}

__global__ __launch_bounds__(32) void disp_scan_kernel() {
    int e = threadIdx.x;
    if (e >= NEXP) return;
    int run = 0;
    for (int s = 0; s < NSEG; s++) {
        g_seg_base[s][e] = run;
        run += g_seg_hist[s][e];
    }
    g_count[e] = run < CAP ? run : CAP;
}

__global__ __launch_bounds__(256) void disp_assign_kernel() {
    __shared__ int s[256][NEXP];
    int t = threadIdx.x, b = blockIdx.x;
    int idx0 = b * SEGSZ + 2 * t;
    int2 ev = *(const int2*)(g_topk_e + idx0);
    float2 wv = *(const float2*)(g_topk_w + idx0);

    int cnt[NEXP];
    #pragma unroll
    for (int e = 0; e < NEXP; e++) cnt[e] = (ev.x == e) + (ev.y == e);
    #pragma unroll
    for (int e = 0; e < NEXP; e++) s[t][e] = cnt[e];
    __syncthreads();
    for (int off = 1; off < 256; off <<= 1) {
        int v[NEXP];
        if (t >= off) {
            #pragma unroll
            for (int e = 0; e < NEXP; e++) v[e] = s[t - off][e];
        }
        __syncthreads();
        if (t >= off) {
            #pragma unroll
            for (int e = 0; e < NEXP; e++) s[t][e] += v[e];
        }
        __syncthreads();
    }
    int pos0 = 0, pos1 = 0;
    #pragma unroll
    for (int e = 0; e < NEXP; e++) {
        int pref = (t == 0 ? 0 : s[t-1][e]) + g_seg_base[b][e];
        if (ev.x == e) pos0 = pref;
        if (ev.y == e) pos1 = pref + (ev.x == e);
    }
    if (pos0 < CAP) {
        int slot = ev.x * CAP + pos0;
        g_slot_token[slot] = idx0 >> 1;
        g_slot_w[slot] = wv.x;
    }
    if (pos1 < CAP) {
        int slot = ev.y * CAP + pos1;
        g_slot_token[slot] = (idx0 + 1) >> 1;
        g_slot_w[slot] = wv.y;
    }
}

// ---------------- fp16 mma.sync GEMMs: CTA 128x128, 4 warps (2x2 of 64x64) ------
#define ROWP32  36
#define ROWB    (ROWP32*4)
#define A_U32   (128*ROWP32)
#define STAGE_U32 (2*A_U32)
#define NSTAGE  3
#define SMEM_BYTES (NSTAGE*STAGE_U32*4)   // 110592

// GEMM1 (per-expert): A gathered from g_zb via slot_token; B rows even=gate odd=up
__global__ __launch_bounds__(128, 2) void gemm1_tc(const __half* __restrict__ w13h, int e) {
    int m0 = blockIdx.y * 128;
    if (m0 >= g_count[e]) return;
    int n0h = blockIdx.x * 64;

    extern __shared__ uint32_t sm[];
    int tid = threadIdx.x;
    uint32_t smBase = smem_u32(sm);
    const __half* Wb = w13h + (size_t)e * 2 * HID * DIM;

    int c8 = tid & 7;
    const __half* aBase[8];
    #pragma unroll
    for (int j = 0; j < 8; j++) {
        int row = (tid >> 3) + 16 * j;
        int tok = g_slot_token[e * CAP + m0 + row];
        aBase[j] = g_zb + (size_t)tok * DIM + c8 * 8;
    }

    #define G1_ISSUE(stage, chunk) do {                                        \
        uint32_t* As_ = sm + (stage) * STAGE_U32;                              \
        uint32_t* Bs_ = As_ + A_U32;                                           \
        int k0_ = (chunk) * 64;                                                \
        _Pragma("unroll")                                                      \
        for (int j = 0; j < 8; j++) {                                          \
            int row = (tid >> 3) + 16 * j;                                     \
            CP_ASYNC16(smem_u32(As_ + row*ROWP32 + c8*4), aBase[j] + k0_);     \
        }                                                                      \
        _Pragma("unroll")                                                      \
        for (int j = 0; j < 8; j++) {                                          \
            int fI = tid + 128*j; int r = fI >> 3; int cc = fI & 7;            \
            int gr = (r & 1) ? (HID + n0h + (r >> 1)) : (n0h + (r >> 1));      \
            CP_ASYNC16(smem_u32(Bs_ + r*ROWP32 + cc*4),                        \
                       Wb + (size_t)gr * DIM + k0_ + cc*8);                    \
        }                                                                      \
    } while (0)

    float c[4][8][4];
    #pragma unroll
    for (int a = 0; a < 4; a++)
        #pragma unroll
        for (int b = 0; b < 8; b++)
            #pragma unroll
            for (int r = 0; r < 4; r++) c[a][b][r] = 0.f;

    int lane = tid & 31, wid = tid >> 5;
    int wr = wid >> 1, wc = wid & 1;
    int qr = lane >> 2, qc = lane & 3;

    uint32_t aLaneOff = (uint32_t)((lane & 15) * ROWB + (lane >> 4) * 16);
    uint32_t bLaneOff = (uint32_t)(((lane >> 4) * 8 + (lane & 7)) * ROWB + ((lane >> 3) & 1) * 16);

    G1_ISSUE(0, 0); CP_COMMIT();
    G1_ISSUE(1, 1); CP_COMMIT();

    const int NCH = DIM / 64;   // 12
    for (int i = 0; i < NCH; i++) {
        int s = i % NSTAGE;
        CP_WAIT1();
        __syncthreads();
        if (i + 2 < NCH) G1_ISSUE((i + 2) % NSTAGE, i + 2);
        CP_COMMIT();
        uint32_t aStage = smBase + (uint32_t)(s * STAGE_U32 * 4);
        uint32_t bStage = aStage + A_U32 * 4;
        #pragma unroll
        for (int kk = 0; kk < 4; kk++) {
            uint32_t a[4][4], b[8][2];
            #pragma unroll
            for (int mt = 0; mt < 4; mt++) {
                uint32_t ad = aStage + aLaneOff + (uint32_t)((wr*64 + mt*16) * ROWB) + kk*32;
                LDSM4(a[mt][0], a[mt][1], a[mt][2], a[mt][3], ad);
            }
            #pragma unroll
            for (int p = 0; p < 4; p++) {
                uint32_t bd = bStage + bLaneOff + (uint32_t)((wc*64 + p*16) * ROWB) + kk*32;
                LDSM4(b[2*p][0], b[2*p][1], b[2*p+1][0], b[2*p+1][1], bd);
            }
            #pragma unroll
            for (int mt = 0; mt < 4; mt++)
                #pragma unroll
                for (int nt = 0; nt < 8; nt++)
                    mma16(c[mt][nt], a[mt], b[nt]);
        }
    }

    __half* H = g_h + (size_t)(e * CAP + m0) * HID;
    #pragma unroll
    for (int mt = 0; mt < 4; mt++) {
        int r0 = wr*64 + mt*16 + qr;
        #pragma unroll
        for (int nt = 0; nt < 8; nt++) {
            int hcol = n0h + wc*32 + nt*4 + qc;
            float g0 = c[mt][nt][0], u0 = c[mt][nt][1];
            float g1 = c[mt][nt][2], u1 = c[mt][nt][3];
            H[(size_t)r0 * HID + hcol]       = __float2half_rn((g0 / (1.f + expf(-g0))) * u0);
            H[(size_t)(r0 + 8) * HID + hcol] = __float2half_rn((g1 / (1.f + expf(-g1))) * u1);
        }
    }
    #undef G1_ISSUE
}

// GEMM2 + fused combine (per-expert)
__global__ __launch_bounds__(128, 2) void gemm2_tc(const __half* __restrict__ w2h,
                                                   const float* __restrict__ x,
                                                   float* __restrict__ out, int e) {
    int count = g_count[e];
    int m0 = blockIdx.y * 128;
    if (m0 >= count) return;
    int n0 = blockIdx.x * 128;

    extern __shared__ uint32_t sm[];
    int tid = threadIdx.x;
    uint32_t smBase = smem_u32(sm);
    const __half* Ab = g_h + (size_t)(e * CAP + m0) * HID;
    const __half* Wb = w2h + (size_t)e * DIM * HID + (size_t)n0 * HID;

    #define G2_ISSUE(stage, chunk) do {                                        \
        uint32_t* As_ = sm + (stage) * STAGE_U32;                              \
        uint32_t* Bs_ = As_ + A_U32;                                           \
        int k0_ = (chunk) * 64;                                                \
        _Pragma("unroll")                                                      \
        for (int j = 0; j < 8; j++) {                                          \
            int fI = tid + 128*j; int row = fI >> 3; int cc = fI & 7;          \
            CP_ASYNC16(smem_u32(As_ + row*ROWP32 + cc*4),                      \
                       Ab + (size_t)row * HID + k0_ + cc*8);                   \
        }                                                                      \
        _Pragma("unroll")                                                      \
        for (int j = 0; j < 8; j++) {                                          \
            int fI = tid + 128*j; int r = fI >> 3; int cc = fI & 7;            \
            CP_ASYNC16(smem_u32(Bs_ + r*ROWP32 + cc*4),                        \
                       Wb + (size_t)r * HID + k0_ + cc*8);                     \
        }                                                                      \
    } while (0)

    float c[4][8][4];
    #pragma unroll
    for (int a = 0; a < 4; a++)
        #pragma unroll
        for (int b = 0; b < 8; b++)
            #pragma unroll
            for (int r = 0; r < 4; r++) c[a][b][r] = 0.f;

    int lane = tid & 31, wid = tid >> 5;
    int wr = wid >> 1, wc = wid & 1;
    int qr = lane >> 2, qc = lane & 3;

    uint32_t aLaneOff = (uint32_t)((lane & 15) * ROWB + (lane >> 4) * 16);
    uint32_t bLaneOff = (uint32_t)(((lane >> 4) * 8 + (lane & 7)) * ROWB + ((lane >> 3) & 1) * 16);

    G2_ISSUE(0, 0); CP_COMMIT();
    G2_ISSUE(1, 1); CP_COMMIT();

    const int NCH = HID / 64;   // 32
    for (int i = 0; i < NCH; i++) {
        int s = i % NSTAGE;
        CP_WAIT1();
        __syncthreads();
        if (i + 2 < NCH) G2_ISSUE((i + 2) % NSTAGE, i + 2);
        CP_COMMIT();
        uint32_t aStage = smBase + (uint32_t)(s * STAGE_U32 * 4);
        uint32_t bStage = aStage + A_U32 * 4;
        #pragma unroll
        for (int kk = 0; kk < 4; kk++) {
            uint32_t a[4][4], b[8][2];
            #pragma unroll
            for (int mt = 0; mt < 4; mt++) {
                uint32_t ad = aStage + aLaneOff + (uint32_t)((wr*64 + mt*16) * ROWB) + kk*32;
                LDSM4(a[mt][0], a[mt][1], a[mt][2], a[mt][3], ad);
            }
            #pragma unroll
            for (int p = 0; p < 4; p++) {
                uint32_t bd = bStage + bLaneOff + (uint32_t)((wc*64 + p*16) * ROWB) + kk*32;
                LDSM4(b[2*p][0], b[2*p][1], b[2*p+1][0], b[2*p+1][1], bd);
            }
            #pragma unroll
            for (int mt = 0; mt < 4; mt++)
                #pragma unroll
                for (int nt = 0; nt < 8; nt++)
                    mma16(c[mt][nt], a[mt], b[nt]);
        }
    }

    #pragma unroll
    for (int mt = 0; mt < 4; mt++) {
        int r0 = wr*64 + mt*16 + qr;
        int r1 = r0 + 8;
        bool v0 = (m0 + r0) < count;
        bool v1 = (m0 + r1) < count;
        int slot0 = e * CAP + m0 + r0;
        int slot1 = slot0 + 8;
        int t0 = v0 ? g_slot_token[slot0] : 0;
        int t1 = v1 ? g_slot_token[slot1] : 0;
        float cw0 = v0 ? g_slot_w[slot0] : 0.f;
        float cw1 = v1 ? g_slot_w[slot1] : 0.f;
        #pragma unroll
        for (int nt = 0; nt < 8; nt++) {
            int col = n0 + wc*64 + nt*8 + qc*2;
            if (v0) {
                float2 x0 = *(const float2*)&x[(size_t)t0 * DIM + col];
                atomicAdd(&out[(size_t)t0 * DIM + col],     cw0 * (x0.x + c[mt][nt][0]));
                atomicAdd(&out[(size_t)t0 * DIM + col + 1], cw0 * (x0.y + c[mt][nt][1]));
            }
            if (v1) {
                float2 x1 = *(const float2*)&x[(size_t)t1 * DIM + col];
                atomicAdd(&out[(size_t)t1 * DIM + col],     cw1 * (x1.x + c[mt][nt][2]));
                atomicAdd(&out[(size_t)t1 * DIM + col + 1], cw1 * (x1.y + c[mt][nt][3]));
            }
        }
    }
    #undef G2_ISSUE
}

// ---------------- launch: 2-stream per-expert pipeline (no new streams vs R10) --
extern "C" void kernel_launch(void* const* d_in, const int* in_sizes, int n_in,
                              void* d_out, int out_size) {
    const float* x      = (const float*)d_in[0];
    const float* gate_w = (const float*)d_in[1];
    const float* w13    = (const float*)d_in[2];
    const float* w2     = (const float*)d_in[3];
    const float* norm_w = (const float*)d_in[4];
    float* out = (float*)d_out;

    static cudaStream_t sA = nullptr, sB = nullptr;
    static cudaEvent_t ev0 = nullptr, evW13 = nullptr, evW2 = nullptr, evDisp = nullptr,
                       evDoneA = nullptr, evDoneB = nullptr;
    static bool inited = false;
    if (!inited) {
        cudaStreamCreateWithFlags(&sA, cudaStreamNonBlocking);
        cudaStreamCreateWithFlags(&sB, cudaStreamNonBlocking);
        cudaEventCreateWithFlags(&ev0,    cudaEventDisableTiming);
        cudaEventCreateWithFlags(&evW13,  cudaEventDisableTiming);
        cudaEventCreateWithFlags(&evW2,   cudaEventDisableTiming);
        cudaEventCreateWithFlags(&evDisp, cudaEventDisableTiming);
        cudaEventCreateWithFlags(&evDoneA, cudaEventDisableTiming);
        cudaEventCreateWithFlags(&evDoneB, cudaEventDisableTiming);
        cudaFuncSetAttribute(gemm1_tc, cudaFuncAttributeMaxDynamicSharedMemorySize, SMEM_BYTES);
        cudaFuncSetAttribute(gemm2_tc, cudaFuncAttributeMaxDynamicSharedMemorySize, SMEM_BYTES);
        inited = true;
    }

    __half* w13h; cudaGetSymbolAddress((void**)&w13h, g_w13h);
    __half* w2h;  cudaGetSymbolAddress((void**)&w2h,  g_w2h);

    // fork
    cudaEventRecord(ev0, 0);
    cudaStreamWaitEvent(sA, ev0, 0);
    cudaStreamWaitEvent(sB, ev0, 0);

    // stream A: w13 conversion
    cvt_w13_kernel<<<4096, 256, 0, sA>>>(w13, norm_w, w13h);
    cudaEventRecord(evW13, sA);

    // stream B: w2 conversion + out clear
    cvt_half_kernel<<<4096, 256, 0, sB>>>(w2, w2h, W2N/4);
    cudaMemsetAsync(out, 0, (size_t)N_TOK * DIM * sizeof(float), sB);
    cudaEventRecord(evW2, sB);

    // routing chain on stream0
    router_prep_kernel<<<N_TOK/8, 256>>>(x, gate_w);
    disp_count_kernel <<<NSEG, 256>>>();
    disp_scan_kernel  <<<1, 32>>>();
    disp_assign_kernel<<<NSEG, 256>>>();
    cudaEventRecord(evDisp, 0);

    // cross dependencies: A needs evDisp + evW2 (gemm2 in A); B needs evDisp + evW13
    cudaStreamWaitEvent(sA, evDisp, 0);
    cudaStreamWaitEvent(sA, evW2, 0);
    cudaStreamWaitEvent(sB, evDisp, 0);
    cudaStreamWaitEvent(sB, evW13, 0);

    // even experts on A, odd on B: gemm1(e) -> gemm2(e) pairs, streams backfill each other
    for (int e = 0; e < NEXP; e += 2) {
        gemm1_tc<<<dim3(HID/64, CAP/128), 128, SMEM_BYTES, sA>>>(w13h, e);
        gemm2_tc<<<dim3(DIM/128, CAP/128), 128, SMEM_BYTES, sA>>>(w2h, x, out, e);
        gemm1_tc<<<dim3(HID/64, CAP/128), 128, SMEM_BYTES, sB>>>(w13h, e + 1);
        gemm2_tc<<<dim3(DIM/128, CAP/128), 128, SMEM_BYTES, sB>>>(w2h, x, out, e + 1);
    }
    cudaEventRecord(evDoneA, sA);
    cudaEventRecord(evDoneB, sB);

    // join back to stream0
    cudaStreamWaitEvent(0, evDoneA, 0);
    cudaStreamWaitEvent(0, evDoneB, 0);
}

// round 13
// speedup vs baseline: 1.0094x; 1.0094x over previous
#include <cuda_runtime.h>
#include <cuda_fp16.h>
#include <math.h>
#include <stdint.h>

// Problem constants
#define N_TOK 16384
#define DIM   768
#define NEXP  8
#define HID   2048
#define CAP   5120
#define NK    (N_TOK*2)
#define NSLOT (NEXP*CAP)
#define NSEG  64
#define SEGSZ (NK/NSEG)

#define W13N (NEXP*2*HID*DIM)
#define W2N  (NEXP*DIM*HID)

// ---------------- device scratch ----------------
__device__ int    g_topk_e[NK];
__device__ float  g_topk_w[NK];
__device__ int    g_count[NEXP];
__device__ int    g_slot_token[NSLOT];
__device__ float  g_slot_w[NSLOT];
__device__ int    g_seg_hist[NSEG][NEXP];
__device__ int    g_seg_base[NSEG][NEXP];
__device__ __half g_zb[(size_t)N_TOK*DIM];
__device__ __half g_h[(size_t)NSLOT*HID];
__device__ __half g_w13h[W13N];
__device__ __half g_w2h[W2N];

// ---------------- helpers ----------------
__device__ __forceinline__ uint32_t smem_u32(const void* p) {
    uint32_t a;
    asm("{ .reg .u64 t; cvta.to.shared.u64 t, %1; cvt.u32.u64 %0, t; }" : "=r"(a) : "l"(p));
    return a;
}
#define CP_ASYNC16(s, g) \
    asm volatile("cp.async.cg.shared.global [%0], [%1], 16;" :: "r"(s), "l"(g))
#define CP_COMMIT() asm volatile("cp.async.commit_group;")
#define CP_WAIT1()  asm volatile("cp.async.wait_group 1;")

#define LDSM4(r0, r1, r2, r3, addr) \
    asm volatile("ldmatrix.sync.aligned.m8n8.x4.shared.b16 {%0,%1,%2,%3}, [%4];" \
        : "=r"(r0), "=r"(r1), "=r"(r2), "=r"(r3) : "r"(addr))

__device__ __forceinline__ void mma16(float* c, const uint32_t* a, const uint32_t* b) {
    asm("mma.sync.aligned.m16n8k16.row.col.f32.f16.f16.f32 "
        "{%0,%1,%2,%3}, {%4,%5,%6,%7}, {%8,%9}, {%0,%1,%2,%3};"
        : "+f"(c[0]), "+f"(c[1]), "+f"(c[2]), "+f"(c[3])
        : "r"(a[0]), "r"(a[1]), "r"(a[2]), "r"(a[3]), "r"(b[0]), "r"(b[1]));
}

// ---------------- w13 * norm_w -> half ----------------
__global__ __launch_bounds__(256) void cvt_w13_kernel(const float* __restrict__ src,
                                                      const float* __restrict__ norm_w,
                                                      __half* __restrict__ dst) {
    int i = blockIdx.x * 256 + threadIdx.x;
    int stride = gridDim.x * 256;
    const int ROW4 = DIM / 4;
    for (; i < W13N/4; i += stride) {
        int col4 = i % ROW4;
        int e = i / (2 * HID * ROW4);
        float4 v = ((const float4*)src)[i];
        float4 nw = ((const float4*)(norm_w + e * DIM))[col4];
        __half2 h0 = __floats2half2_rn(v.x * nw.x, v.y * nw.y);
        __half2 h1 = __floats2half2_rn(v.z * nw.z, v.w * nw.w);
        uint2 pk;
        pk.x = *(uint32_t*)&h0;  pk.y = *(uint32_t*)&h1;
        ((uint2*)dst)[i] = pk;
    }
}

// ---------------- w2 -> half ----------------
__global__ __launch_bounds__(256) void cvt_half_kernel(const float* __restrict__ src,
                                                       __half* __restrict__ dst, int n4) {
    int i = blockIdx.x * 256 + threadIdx.x;
    int stride = gridDim.x * 256;
    for (; i < n4; i += stride) {
        float4 v = ((const float4*)src)[i];
        __half2 h0 = __floats2half2_rn(v.x, v.y);
        __half2 h1 = __floats2half2_rn(v.z, v.w);
        uint2 pk;
        pk.x = *(uint32_t*)&h0;  pk.y = *(uint32_t*)&h1;
        ((uint2*)dst)[i] = pk;
    }
}

// ---------------- fused router + prep (float4-vectorized) ----------------
__global__ __launch_bounds__(256) void router_prep_kernel(const float* __restrict__ x,
                                                          const float* __restrict__ gate_w) {
    __shared__ float4 gw4[NEXP * DIM / 4];     // 1536 float4
    int t = threadIdx.x;
    for (int i = t; i < NEXP * DIM / 4; i += 256) gw4[i] = ((const float4*)gate_w)[i];
    __syncthreads();
    int warp = t >> 5, lane = t & 31;
    int token = blockIdx.x * 8 + warp;
    const float4* xr4 = (const float4*)(x + (size_t)token * DIM);

    const int R4 = DIM / 4 / 32;   // 6 float4 per lane
    float4 xv[R4];
    float acc[NEXP];
    float ss = 0.f;
    #pragma unroll
    for (int e = 0; e < NEXP; e++) acc[e] = 0.f;
    #pragma unroll
    for (int i = 0; i < R4; i++) {
        float4 v = xr4[lane + 32*i];
        xv[i] = v;
        ss += v.x*v.x + v.y*v.y + v.z*v.z + v.w*v.w;
        #pragma unroll
        for (int e = 0; e < NEXP; e++) {
            float4 g = gw4[e * (DIM/4) + lane + 32*i];
            acc[e] += v.x*g.x + v.y*g.y + v.z*g.z + v.w*g.w;
        }
    }
    #pragma unroll
    for (int off = 16; off; off >>= 1) ss += __shfl_xor_sync(0xffffffffu, ss, off);
    float scale = 2.f * rsqrtf(4.f * ss / (float)DIM + 1e-6f);
    __half* zr = g_zb + (size_t)token * DIM;
    #pragma unroll
    for (int i = 0; i < R4; i++) {
        __half2 h0 = __floats2half2_rn(xv[i].x * scale, xv[i].y * scale);
        __half2 h1 = __floats2half2_rn(xv[i].z * scale, xv[i].w * scale);
        uint2 pk;
        pk.x = *(uint32_t*)&h0;  pk.y = *(uint32_t*)&h1;
        *(uint2*)&zr[(lane + 32*i) * 4] = pk;
    }

    #pragma unroll
    for (int e = 0; e < NEXP; e++) {
        #pragma unroll
        for (int off = 16; off; off >>= 1)
            acc[e] += __shfl_xor_sync(0xffffffffu, acc[e], off);
    }
    if (lane == 0) {
        int i0 = 0;
        #pragma unroll
        for (int e = 1; e < NEXP; e++) if (acc[e] > acc[i0]) i0 = e;
        int i1 = -1;
        #pragma unroll
        for (int e = 0; e < NEXP; e++) {
            if (e == i0) continue;
            if (i1 < 0 || acc[e] > acc[i1]) i1 = e;
        }
        float l0 = acc[i0], l1 = acc[i1];
        g_topk_e[2*token]   = i0;  g_topk_e[2*token+1] = i1;
        g_topk_w[2*token]   = 1.f / (1.f + expf(l1 - l0));
        g_topk_w[2*token+1] = 1.f / (1.f + expf(l0 - l1));
    }
}

// ---------------- dispatch ----------------
__global__ __launch_bounds__(256) void disp_count_kernel() {
    __shared__ int h[NEXP];
    int t = threadIdx.x, b = blockIdx.x;
    if (t < NEXP) h[t] = 0;
    __syncthreads();
    int2 ev = *(const int2*)(g_topk_e + b * SEGSZ + 2 * t);
    atomicAdd(&h[ev.x], 1);
    atomicAdd(&h[ev.y], 1);
    __syncthreads();
    if (t < NEXP) g_seg_hist[b][t] = h[t];
}

__global__ __launch_bounds__(32) void disp_scan_kernel() {
    int e = threadIdx.x;
    if (e >= NEXP) return;
    int run = 0;
    for (int s = 0; s < NSEG; s++) {
        g_seg_base[s][e] = run;
        run += g_seg_hist[s][e];
    }
    g_count[e] = run < CAP ? run : CAP;
}

__global__ __launch_bounds__(256) void disp_assign_kernel() {
    __shared__ int s[256][NEXP];
    int t = threadIdx.x, b = blockIdx.x;
    int idx0 = b * SEGSZ + 2 * t;
    int2 ev = *(const int2*)(g_topk_e + idx0);
    float2 wv = *(const float2*)(g_topk_w + idx0);

    int cnt[NEXP];
    #pragma unroll
    for (int e = 0; e < NEXP; e++) cnt[e] = (ev.x == e) + (ev.y == e);
    #pragma unroll
    for (int e = 0; e < NEXP; e++) s[t][e] = cnt[e];
    __syncthreads();
    for (int off = 1; off < 256; off <<= 1) {
        int v[NEXP];
        if (t >= off) {
            #pragma unroll
            for (int e = 0; e < NEXP; e++) v[e] = s[t - off][e];
        }
        __syncthreads();
        if (t >= off) {
            #pragma unroll
            for (int e = 0; e < NEXP; e++) s[t][e] += v[e];
        }
        __syncthreads();
    }
    int pos0 = 0, pos1 = 0;
    #pragma unroll
    for (int e = 0; e < NEXP; e++) {
        int pref = (t == 0 ? 0 : s[t-1][e]) + g_seg_base[b][e];
        if (ev.x == e) pos0 = pref;
        if (ev.y == e) pos1 = pref + (ev.x == e);
    }
    if (pos0 < CAP) {
        int slot = ev.x * CAP + pos0;
        g_slot_token[slot] = idx0 >> 1;
        g_slot_w[slot] = wv.x;
    }
    if (pos1 < CAP) {
        int slot = ev.y * CAP + pos1;
        g_slot_token[slot] = (idx0 + 1) >> 1;
        g_slot_w[slot] = wv.y;
    }
}

// ---------------- fp16 mma.sync GEMMs: CTA 128x128, 4 warps (2x2 of 64x64) ------
#define ROWP32  36
#define ROWB    (ROWP32*4)
#define A_U32   (128*ROWP32)
#define STAGE_U32 (2*A_U32)
#define NSTAGE  3
#define SMEM_BYTES (NSTAGE*STAGE_U32*4)   // 110592

// GEMM1: A gathered from g_zb via slot_token; B rows even=gate odd=up; K=DIM
__global__ __launch_bounds__(128, 2) void gemm1_tc(const __half* __restrict__ w13h) {
    int e = blockIdx.z;
    int m0 = blockIdx.y * 128;
    if (m0 >= g_count[e]) return;
    int n0h = blockIdx.x * 64;

    extern __shared__ uint32_t sm[];
    int tid = threadIdx.x;
    uint32_t smBase = smem_u32(sm);
    const __half* Wb = w13h + (size_t)e * 2 * HID * DIM;

    int c8 = tid & 7;
    const __half* aBase[8];
    #pragma unroll
    for (int j = 0; j < 8; j++) {
        int row = (tid >> 3) + 16 * j;
        int tok = g_slot_token[e * CAP + m0 + row];
        aBase[j] = g_zb + (size_t)tok * DIM + c8 * 8;
    }

    #define G1_ISSUE(stage, chunk) do {                                        \
        uint32_t* As_ = sm + (stage) * STAGE_U32;                              \
        uint32_t* Bs_ = As_ + A_U32;                                           \
        int k0_ = (chunk) * 64;                                                \
        _Pragma("unroll")                                                      \
        for (int j = 0; j < 8; j++) {                                          \
            int row = (tid >> 3) + 16 * j;                                     \
            CP_ASYNC16(smem_u32(As_ + row*ROWP32 + c8*4), aBase[j] + k0_);     \
        }                                                                      \
        _Pragma("unroll")                                                      \
        for (int j = 0; j < 8; j++) {                                          \
            int fI = tid + 128*j; int r = fI >> 3; int cc = fI & 7;            \
            int gr = (r & 1) ? (HID + n0h + (r >> 1)) : (n0h + (r >> 1));      \
            CP_ASYNC16(smem_u32(Bs_ + r*ROWP32 + cc*4),                        \
                       Wb + (size_t)gr * DIM + k0_ + cc*8);                    \
        }                                                                      \
    } while (0)

    float c[4][8][4];
    #pragma unroll
    for (int a = 0; a < 4; a++)
        #pragma unroll
        for (int b = 0; b < 8; b++)
            #pragma unroll
            for (int r = 0; r < 4; r++) c[a][b][r] = 0.f;

    int lane = tid & 31, wid = tid >> 5;
    int wr = wid >> 1, wc = wid & 1;
    int qr = lane >> 2, qc = lane & 3;

    uint32_t aLaneOff = (uint32_t)((lane & 15) * ROWB + (lane >> 4) * 16);
    uint32_t bLaneOff = (uint32_t)(((lane >> 4) * 8 + (lane & 7)) * ROWB + ((lane >> 3) & 1) * 16);

    G1_ISSUE(0, 0); CP_COMMIT();
    G1_ISSUE(1, 1); CP_COMMIT();

    const int NCH = DIM / 64;   // 12
    for (int i = 0; i < NCH; i++) {
        int s = i % NSTAGE;
        CP_WAIT1();
        __syncthreads();
        if (i + 2 < NCH) G1_ISSUE((i + 2) % NSTAGE, i + 2);
        CP_COMMIT();
        uint32_t aStage = smBase + (uint32_t)(s * STAGE_U32 * 4);
        uint32_t bStage = aStage + A_U32 * 4;
        #pragma unroll
        for (int kk = 0; kk < 4; kk++) {
            uint32_t a[4][4], b[8][2];
            #pragma unroll
            for (int mt = 0; mt < 4; mt++) {
                uint32_t ad = aStage + aLaneOff + (uint32_t)((wr*64 + mt*16) * ROWB) + kk*32;
                LDSM4(a[mt][0], a[mt][1], a[mt][2], a[mt][3], ad);
            }
            #pragma unroll
            for (int p = 0; p < 4; p++) {
                uint32_t bd = bStage + bLaneOff + (uint32_t)((wc*64 + p*16) * ROWB) + kk*32;
                LDSM4(b[2*p][0], b[2*p][1], b[2*p+1][0], b[2*p+1][1], bd);
            }
            #pragma unroll
            for (int mt = 0; mt < 4; mt++)
                #pragma unroll
                for (int nt = 0; nt < 8; nt++)
                    mma16(c[mt][nt], a[mt], b[nt]);
        }
    }

    __half* H = g_h + (size_t)(e * CAP + m0) * HID;
    #pragma unroll
    for (int mt = 0; mt < 4; mt++) {
        int r0 = wr*64 + mt*16 + qr;
        #pragma unroll
        for (int nt = 0; nt < 8; nt++) {
            int hcol = n0h + wc*32 + nt*4 + qc;
            float g0 = c[mt][nt][0], u0 = c[mt][nt][1];
            float g1 = c[mt][nt][2], u1 = c[mt][nt][3];
            H[(size_t)r0 * HID + hcol]       = __float2half_rn((g0 / (1.f + expf(-g0))) * u0);
            H[(size_t)(r0 + 8) * HID + hcol] = __float2half_rn((g1 / (1.f + expf(-g1))) * u1);
        }
    }
    #undef G1_ISSUE
}

// GEMM2 + fused combine: D = h @ w2^T; out[token] += cw * (x[token] + D)
__global__ __launch_bounds__(128, 2) void gemm2_tc(const __half* __restrict__ w2h,
                                                   const float* __restrict__ x,
                                                   float* __restrict__ out) {
    int e = blockIdx.z;
    int count = g_count[e];
    int m0 = blockIdx.y * 128;
    if (m0 >= count) return;
    int n0 = blockIdx.x * 128;

    extern __shared__ uint32_t sm[];
    int tid = threadIdx.x;
    uint32_t smBase = smem_u32(sm);
    const __half* Ab = g_h + (size_t)(e * CAP + m0) * HID;
    const __half* Wb = w2h + (size_t)e * DIM * HID + (size_t)n0 * HID;

    #define G2_ISSUE(stage, chunk) do {                                        \
        uint32_t* As_ = sm + (stage) * STAGE_U32;                              \
        uint32_t* Bs_ = As_ + A_U32;                                           \
        int k0_ = (chunk) * 64;                                                \
        _Pragma("unroll")                                                      \
        for (int j = 0; j < 8; j++) {                                          \
            int fI = tid + 128*j; int row = fI >> 3; int cc = fI & 7;          \
            CP_ASYNC16(smem_u32(As_ + row*ROWP32 + cc*4),                      \
                       Ab + (size_t)row * HID + k0_ + cc*8);                   \
        }                                                                      \
        _Pragma("unroll")                                                      \
        for (int j = 0; j < 8; j++) {                                          \
            int fI = tid + 128*j; int r = fI >> 3; int cc = fI & 7;            \
            CP_ASYNC16(smem_u32(Bs_ + r*ROWP32 + cc*4),                        \
                       Wb + (size_t)r * HID + k0_ + cc*8);                     \
        }                                                                      \
    } while (0)

    float c[4][8][4];
    #pragma unroll
    for (int a = 0; a < 4; a++)
        #pragma unroll
        for (int b = 0; b < 8; b++)
            #pragma unroll
            for (int r = 0; r < 4; r++) c[a][b][r] = 0.f;

    int lane = tid & 31, wid = tid >> 5;
    int wr = wid >> 1, wc = wid & 1;
    int qr = lane >> 2, qc = lane & 3;

    uint32_t aLaneOff = (uint32_t)((lane & 15) * ROWB + (lane >> 4) * 16);
    uint32_t bLaneOff = (uint32_t)(((lane >> 4) * 8 + (lane & 7)) * ROWB + ((lane >> 3) & 1) * 16);

    G2_ISSUE(0, 0); CP_COMMIT();
    G2_ISSUE(1, 1); CP_COMMIT();

    const int NCH = HID / 64;   // 32
    for (int i = 0; i < NCH; i++) {
        int s = i % NSTAGE;
        CP_WAIT1();
        __syncthreads();
        if (i + 2 < NCH) G2_ISSUE((i + 2) % NSTAGE, i + 2);
        CP_COMMIT();
        uint32_t aStage = smBase + (uint32_t)(s * STAGE_U32 * 4);
        uint32_t bStage = aStage + A_U32 * 4;
        #pragma unroll
        for (int kk = 0; kk < 4; kk++) {
            uint32_t a[4][4], b[8][2];
            #pragma unroll
            for (int mt = 0; mt < 4; mt++) {
                uint32_t ad = aStage + aLaneOff + (uint32_t)((wr*64 + mt*16) * ROWB) + kk*32;
                LDSM4(a[mt][0], a[mt][1], a[mt][2], a[mt][3], ad);
            }
            #pragma unroll
            for (int p = 0; p < 4; p++) {
                uint32_t bd = bStage + bLaneOff + (uint32_t)((wc*64 + p*16) * ROWB) + kk*32;
                LDSM4(b[2*p][0], b[2*p][1], b[2*p+1][0], b[2*p+1][1], bd);
            }
            #pragma unroll
            for (int mt = 0; mt < 4; mt++)
                #pragma unroll
                for (int nt = 0; nt < 8; nt++)
                    mma16(c[mt][nt], a[mt], b[nt]);
        }
    }

    #pragma unroll
    for (int mt = 0; mt < 4; mt++) {
        int r0 = wr*64 + mt*16 + qr;
        int r1 = r0 + 8;
        bool v0 = (m0 + r0) < count;
        bool v1 = (m0 + r1) < count;
        int slot0 = e * CAP + m0 + r0;
        int slot1 = slot0 + 8;
        int t0 = v0 ? g_slot_token[slot0] : 0;
        int t1 = v1 ? g_slot_token[slot1] : 0;
        float cw0 = v0 ? g_slot_w[slot0] : 0.f;
        float cw1 = v1 ? g_slot_w[slot1] : 0.f;
        #pragma unroll
        for (int nt = 0; nt < 8; nt++) {
            int col = n0 + wc*64 + nt*8 + qc*2;
            if (v0) {
                float2 x0 = *(const float2*)&x[(size_t)t0 * DIM + col];
                atomicAdd(&out[(size_t)t0 * DIM + col],     cw0 * (x0.x + c[mt][nt][0]));
                atomicAdd(&out[(size_t)t0 * DIM + col + 1], cw0 * (x0.y + c[mt][nt][1]));
            }
            if (v1) {
                float2 x1 = *(const float2*)&x[(size_t)t1 * DIM + col];
                atomicAdd(&out[(size_t)t1 * DIM + col],     cw1 * (x1.x + c[mt][nt][2]));
                atomicAdd(&out[(size_t)t1 * DIM + col + 1], cw1 * (x1.y + c[mt][nt][3]));
            }
        }
    }
    #undef G2_ISSUE
}

// ---------------- launch: R10 fork/join structure ----------------
extern "C" void kernel_launch(void* const* d_in, const int* in_sizes, int n_in,
                              void* d_out, int out_size) {
    const float* x      = (const float*)d_in[0];
    const float* gate_w = (const float*)d_in[1];
    const float* w13    = (const float*)d_in[2];
    const float* w2     = (const float*)d_in[3];
    const float* norm_w = (const float*)d_in[4];
    float* out = (float*)d_out;

    static cudaStream_t s1 = nullptr, s2 = nullptr;
    static cudaEvent_t ev0 = nullptr, ev1 = nullptr, ev2 = nullptr;
    static bool inited = false;
    if (!inited) {
        cudaStreamCreateWithFlags(&s1, cudaStreamNonBlocking);
        cudaStreamCreateWithFlags(&s2, cudaStreamNonBlocking);
        cudaEventCreateWithFlags(&ev0, cudaEventDisableTiming);
        cudaEventCreateWithFlags(&ev1, cudaEventDisableTiming);
        cudaEventCreateWithFlags(&ev2, cudaEventDisableTiming);
        cudaFuncSetAttribute(gemm1_tc, cudaFuncAttributeMaxDynamicSharedMemorySize, SMEM_BYTES);
        cudaFuncSetAttribute(gemm2_tc, cudaFuncAttributeMaxDynamicSharedMemorySize, SMEM_BYTES);
        inited = true;
    }

    __half* w13h; cudaGetSymbolAddress((void**)&w13h, g_w13h);
    __half* w2h;  cudaGetSymbolAddress((void**)&w2h,  g_w2h);

    // fork
    cudaEventRecord(ev0, 0);
    cudaStreamWaitEvent(s1, ev0, 0);
    cudaStreamWaitEvent(s2, ev0, 0);

    // s1: gemm1's weight dependency
    cvt_w13_kernel<<<4096, 256, 0, s1>>>(w13, norm_w, w13h);
    cudaEventRecord(ev1, s1);

    // s2: gemm2-only dependencies (overlap with gemm1)
    cvt_half_kernel<<<4096, 256, 0, s2>>>(w2, w2h, W2N/4);
    cudaMemsetAsync(out, 0, (size_t)N_TOK * DIM * sizeof(float), s2);
    cudaEventRecord(ev2, s2);

    // stream0: routing chain
    router_prep_kernel<<<N_TOK/8, 256>>>(x, gate_w);
    disp_count_kernel <<<NSEG, 256>>>();
    disp_scan_kernel  <<<1, 32>>>();
    disp_assign_kernel<<<NSEG, 256>>>();

    // join s1, run gemm1
    cudaStreamWaitEvent(0, ev1, 0);
    gemm1_tc<<<dim3(HID/64, CAP/128, NEXP), 128, SMEM_BYTES>>>(w13h);

    // join s2, run gemm2
    cudaStreamWaitEvent(0, ev2, 0);
    gemm2_tc<<<dim3(DIM/128, CAP/128, NEXP), 128, SMEM_BYTES>>>(w2h, x, out);
}